// round 14
// baseline (speedup 1.0000x reference)
#include <cuda_runtime.h>
#include <cuda_fp16.h>
#include <math.h>
#include <stdint.h>

#define N_NODES 65536
#define N_EDGES 524288
#define C 128
#define L 3
#define BN_EPS 1e-5f

// ---------------- scratch (device globals; no dynamic allocation) ----------------
__device__ float  g_h[N_NODES * C];       // layer output (input for next layer)
__device__ float  g_neigh[N_NODES * C];   // aggregated raw neighbor features (already /deg)
__device__ float  g_wbar[N_NODES];        // (sum of edge weights)/deg per node
__device__ float2 g_edge[N_EDGES];        // CSR-by-dst packed records: (src bits, log1p(w))
__device__ int    g_degcnt[N_NODES];
__device__ int    g_off[N_NODES + 1];
__device__ int    g_cursor[N_NODES];
__device__ float  g_deginv[N_NODES];
__device__ float  g_stats[L * 2 * C];     // per-layer [sum(C) | sumsq(C)]
// pre-packed fp16 weight fragments in mma.sync per-lane order:
// [l][chunk][kstep(8)][nt16(16)][lane(32)] -> uint2 {b0, b1} (f16x2 each)
#define BPK_PER_CHUNK 4096
__device__ __align__(16) uint2 g_Bpk[L * 2 * BPK_PER_CHUNK];

// ---------------- helpers ----------------
__device__ __forceinline__ uint32_t pack_f16x2(float2 v) {
    __half2 h = __float22half2_rn(v);
    return *(uint32_t*)&h;
}
__device__ __forceinline__ void cvt_hilo_f16(float2 v, uint32_t& hi, uint32_t& lo) {
    __half2 h = __float22half2_rn(v);
    hi = *(uint32_t*)&h;
    float2 hf = __half22float2(h);
    __half2 l = __float22half2_rn(make_float2(v.x - hf.x, v.y - hf.y));
    lo = *(uint32_t*)&l;
}
__device__ __forceinline__ void mma_f16(float* d, const uint32_t* a, uint32_t b0, uint32_t b1) {
    asm volatile(
        "mma.sync.aligned.m16n8k16.row.col.f32.f16.f16.f32 "
        "{%0,%1,%2,%3}, {%4,%5,%6,%7}, {%8,%9}, {%0,%1,%2,%3};"
        : "+f"(d[0]), "+f"(d[1]), "+f"(d[2]), "+f"(d[3])
        : "r"(a[0]), "r"(a[1]), "r"(a[2]), "r"(a[3]), "r"(b0), "r"(b1));
}

// ---------------- prep ----------------
__global__ void k_prep0() {
    int i = blockIdx.x * blockDim.x + threadIdx.x;
    if (i < N_NODES) g_degcnt[i] = 0;
    if (i < L * 2 * C) g_stats[i] = 0.0f;
}
__global__ void k_count(const int* __restrict__ dst) {
    int e = blockIdx.x * blockDim.x + threadIdx.x;
    if (e < N_EDGES) atomicAdd(&g_degcnt[dst[e]], 1);
}
__global__ void k_scan() {
    __shared__ int sp[1024];
    int t = threadIdx.x;
    int base = t * 64;
    int sum = 0;
    #pragma unroll 4
    for (int i = 0; i < 64; i++) sum += g_degcnt[base + i];
    sp[t] = sum;
    __syncthreads();
    for (int o = 1; o < 1024; o <<= 1) {
        int v = (t >= o) ? sp[t - o] : 0;
        __syncthreads();
        sp[t] += v;
        __syncthreads();
    }
    int run = sp[t] - sum;
    for (int i = 0; i < 64; i++) {
        int cnt = g_degcnt[base + i];
        g_off[base + i] = run;
        g_cursor[base + i] = run;
        g_deginv[base + i] = 1.0f / fmaxf((float)cnt, 1.0f);
        run += cnt;
    }
    if (t == 1023) g_off[N_NODES] = run;
}
__global__ void k_scatter(const int* __restrict__ src, const int* __restrict__ dst,
                          const float* __restrict__ ew) {
    int e = blockIdx.x * blockDim.x + threadIdx.x;
    if (e >= N_EDGES) return;
    int p = atomicAdd(&g_cursor[dst[e]], 1);
    g_edge[p] = make_float2(__int_as_float(src[e]), log1pf(ew[e]));
}

// ---------------- prep: weights -> pre-packed fp16 mma fragments ----------
__global__ void k_wprep(const float* __restrict__ Ws, const float* __restrict__ Wn) {
    int i = blockIdx.x * blockDim.x + threadIdx.x;   // 24576
    if (i >= L * 2 * BPK_PER_CHUNK) return;
    int lane  = i & 31;
    int nt    = (i >> 5) & 15;
    int kstep = (i >> 9) & 7;
    int chunk = (i >> 12) & 1;
    int l     = i >> 13;
    const float* W = (chunk ? Wn : Ws) + (size_t)l * 16384;
    int k0 = kstep * 16 + (lane & 3) * 2;
    int n  = nt * 8 + (lane >> 2);
    uint32_t b0 = pack_f16x2(make_float2(W[(k0 + 0) * 128 + n], W[(k0 + 1) * 128 + n]));
    uint32_t b1 = pack_f16x2(make_float2(W[(k0 + 8) * 128 + n], W[(k0 + 9) * 128 + n]));
    g_Bpk[i] = make_uint2(b0, b1);
}

// ---------------- one-time: BN column stats of x (layer 0) ----------------
__global__ void k_stats(const float* __restrict__ x) {
    int tid = threadIdx.x;
    int c = tid & (C - 1);
    int rr = tid >> 7;
    float s = 0.0f, s2 = 0.0f;
    for (int r = blockIdx.x * 2 + rr; r < N_NODES; r += gridDim.x * 2) {
        float v = x[(size_t)r * C + c];
        s += v; s2 += v * v;
    }
    atomicAdd(&g_stats[c], s);
    atomicAdd(&g_stats[C + c], s2);
}

// ---------------- per-layer: raw mean aggregation + wbar (R9/R6 version) ----------
__global__ void k_aggr(const float* __restrict__ in) {
    int n = (blockIdx.x * blockDim.x + threadIdx.x) >> 5;
    int lane = threadIdx.x & 31;
    if (n >= N_NODES) return;
    int beg = g_off[n], end = g_off[n + 1];
    const float4* in4 = (const float4*)in;
    float4 a0 = make_float4(0.f, 0.f, 0.f, 0.f);
    float4 a1 = make_float4(0.f, 0.f, 0.f, 0.f);
    float ws = 0.f;
    int i = beg;
    for (; i + 4 <= end; i += 4) {
        float2 e0 = g_edge[i],     e1 = g_edge[i + 1];
        float2 e2 = g_edge[i + 2], e3 = g_edge[i + 3];
        float4 v0 = __ldg(&in4[(size_t)__float_as_int(e0.x) * 32 + lane]);
        float4 v1 = __ldg(&in4[(size_t)__float_as_int(e1.x) * 32 + lane]);
        float4 v2 = __ldg(&in4[(size_t)__float_as_int(e2.x) * 32 + lane]);
        float4 v3 = __ldg(&in4[(size_t)__float_as_int(e3.x) * 32 + lane]);
        a0.x += e0.y * v0.x; a0.y += e0.y * v0.y; a0.z += e0.y * v0.z; a0.w += e0.y * v0.w;
        a1.x += e1.y * v1.x; a1.y += e1.y * v1.y; a1.z += e1.y * v1.z; a1.w += e1.y * v1.w;
        a0.x += e2.y * v2.x; a0.y += e2.y * v2.y; a0.z += e2.y * v2.z; a0.w += e2.y * v2.w;
        a1.x += e3.y * v3.x; a1.y += e3.y * v3.y; a1.z += e3.y * v3.z; a1.w += e3.y * v3.w;
        ws += (e0.y + e1.y) + (e2.y + e3.y);
    }
    for (; i < end; i++) {
        float2 e = g_edge[i];
        float4 v = __ldg(&in4[(size_t)__float_as_int(e.x) * 32 + lane]);
        a0.x += e.y * v.x; a0.y += e.y * v.y; a0.z += e.y * v.z; a0.w += e.y * v.w;
        ws += e.y;
    }
    float di = g_deginv[n];
    float4 acc = make_float4((a0.x + a1.x) * di, (a0.y + a1.y) * di,
                             (a0.z + a1.z) * di, (a0.w + a1.w) * di);
    ((float4*)g_neigh)[(size_t)n * 32 + lane] = acc;
    if (lane == 0) g_wbar[n] = ws * di;
}

// ---------------- per-layer: 2-pass fp16 mma.sync dual GEMM, fused BN (R9) ----------
#define GEMM_SMEM (32768 + 2048)

__global__ __launch_bounds__(256, 2)
void k_gemm(int l, const float* __restrict__ Ain,
            const float* __restrict__ gamma, const float* __restrict__ beta,
            const float* __restrict__ bias,
            const float* __restrict__ lin_w, const float* __restrict__ lin_b,
            float* __restrict__ out, int mode) {
    extern __shared__ unsigned char dyn[];
    uint2* sB    = (uint2*)dyn;                 // 32KB: packed fp16 B fragments
    float* sSc   = (float*)(dyn + 32768);       // 128
    float* sSh   = sSc + 128;                   // 128
    float* sStat = sSh + 128;                   // 256

    int tid = threadIdx.x, wid = tid >> 5, lane = tid & 31;
    int row0 = blockIdx.x * 128;

    if (tid < 128) {
        float sum = g_stats[l * 2 * C + tid];
        float sq  = g_stats[l * 2 * C + C + tid];
        float mu  = sum * (1.0f / N_NODES);
        float var = sq * (1.0f / N_NODES) - mu * mu;
        float sc  = gamma[l * C + tid] * rsqrtf(var + BN_EPS);
        sSc[tid] = sc;
        sSh[tid] = beta[l * C + tid] - mu * sc;
    }
    if (tid < 256) sStat[tid] = 0.0f;

    float acc[16][4];
    #pragma unroll
    for (int nt = 0; nt < 16; nt++)
        #pragma unroll
        for (int q = 0; q < 4; q++) acc[nt][q] = 0.0f;

    int ar = row0 + wid * 16 + (lane >> 2);
    int ak = (lane & 3) * 2;
    float wb0 = g_wbar[ar], wb1 = g_wbar[ar + 8];

    #pragma unroll 1
    for (int chunk = 0; chunk < 2; chunk++) {
        if (chunk) __syncthreads();
        {
            const uint4* src = (const uint4*)(g_Bpk + (size_t)(l * 2 + chunk) * BPK_PER_CHUNK);
            uint4* dst = (uint4*)sB;
            #pragma unroll
            for (int it = 0; it < 8; it++) dst[it * 256 + tid] = src[it * 256 + tid];
        }
        __syncthreads();

        const float* Asrc = chunk ? g_neigh : Ain;
        float m0 = chunk ? wb0 : 1.0f;
        float m1 = chunk ? wb1 : 1.0f;

        #pragma unroll 2
        for (int ks = 0; ks < 8; ks++) {
            int kk = ks * 16 + ak;
            float2 scA = *(const float2*)&sSc[kk];
            float2 scB = *(const float2*)&sSc[kk + 8];
            float2 shA = *(const float2*)&sSh[kk];
            float2 shB = *(const float2*)&sSh[kk + 8];

            const float* p = Asrc + (size_t)ar * C + kk;
            float2 v0 = *(const float2*)(p);
            float2 v1 = *(const float2*)(p + 8 * C);
            float2 v2 = *(const float2*)(p + 8);
            float2 v3 = *(const float2*)(p + 8 * C + 8);
            v0.x = v0.x * scA.x + shA.x * m0; v0.y = v0.y * scA.y + shA.y * m0;
            v1.x = v1.x * scA.x + shA.x * m1; v1.y = v1.y * scA.y + shA.y * m1;
            v2.x = v2.x * scB.x + shB.x * m0; v2.y = v2.y * scB.y + shB.y * m0;
            v3.x = v3.x * scB.x + shB.x * m1; v3.y = v3.y * scB.y + shB.y * m1;

            uint32_t ahi[4], alo[4];
            cvt_hilo_f16(v0, ahi[0], alo[0]);
            cvt_hilo_f16(v1, ahi[1], alo[1]);
            cvt_hilo_f16(v2, ahi[2], alo[2]);
            cvt_hilo_f16(v3, ahi[3], alo[3]);

            #pragma unroll
            for (int nt = 0; nt < 16; nt++) {
                uint2 b = sB[(ks * 16 + nt) * 32 + lane];
                mma_f16(acc[nt], ahi, b.x, b.y);
                mma_f16(acc[nt], alo, b.x, b.y);
            }
        }
    }

    if (mode == 0) {
        #pragma unroll
        for (int nt = 0; nt < 16; nt++) {
            int col = nt * 8 + (lane & 3) * 2;
            float b0 = bias[col], b1 = bias[col + 1];
            float o00 = fmaxf(acc[nt][0] + b0, 0.f);
            float o01 = fmaxf(acc[nt][1] + b1, 0.f);
            float o10 = fmaxf(acc[nt][2] + b0, 0.f);
            float o11 = fmaxf(acc[nt][3] + b1, 0.f);
            *(float2*)(g_h + (size_t)ar * C + col)       = make_float2(o00, o01);
            *(float2*)(g_h + (size_t)(ar + 8) * C + col) = make_float2(o10, o11);
            float s0 = o00 + o10, s1 = o01 + o11;
            float q0 = o00 * o00 + o10 * o10, q1 = o01 * o01 + o11 * o11;
            #pragma unroll
            for (int off = 16; off >= 4; off >>= 1) {
                s0 += __shfl_down_sync(0xffffffffu, s0, off);
                s1 += __shfl_down_sync(0xffffffffu, s1, off);
                q0 += __shfl_down_sync(0xffffffffu, q0, off);
                q1 += __shfl_down_sync(0xffffffffu, q1, off);
            }
            if (lane < 4) {
                atomicAdd(&sStat[col],           s0);
                atomicAdd(&sStat[col + 1],       s1);
                atomicAdd(&sStat[128 + col],     q0);
                atomicAdd(&sStat[128 + col + 1], q1);
            }
        }
        __syncthreads();
        if (tid < 128) {
            atomicAdd(&g_stats[(l + 1) * 2 * C + tid],     sStat[tid]);
            atomicAdd(&g_stats[(l + 1) * 2 * C + C + tid], sStat[128 + tid]);
        }
    } else {
        float p0 = 0.f, p1 = 0.f;
        #pragma unroll
        for (int nt = 0; nt < 16; nt++) {
            int col = nt * 8 + (lane & 3) * 2;
            float b0 = bias[col], b1 = bias[col + 1];
            float lw0 = lin_w[col], lw1 = lin_w[col + 1];
            float o00 = fmaxf(acc[nt][0] + b0, 0.f);
            float o01 = fmaxf(acc[nt][1] + b1, 0.f);
            float o10 = fmaxf(acc[nt][2] + b0, 0.f);
            float o11 = fmaxf(acc[nt][3] + b1, 0.f);
            p0 += o00 * lw0 + o01 * lw1;
            p1 += o10 * lw0 + o11 * lw1;
        }
        p0 += __shfl_xor_sync(0xffffffffu, p0, 1);
        p0 += __shfl_xor_sync(0xffffffffu, p0, 2);
        p1 += __shfl_xor_sync(0xffffffffu, p1, 1);
        p1 += __shfl_xor_sync(0xffffffffu, p1, 2);
        if ((lane & 3) == 0) {
            float lb = lin_b[0];
            out[ar] = p0 + lb;
            out[ar + 8] = p1 + lb;
        }
    }
}

// ---------------- launch ----------------
// MEASUREMENT ROUND: duplicates of idempotent kernels added to extract per-kernel
// times from the total: dur = base + 2*T_aggr + 2*T_gemm(mode1).
extern "C" void kernel_launch(void* const* d_in, const int* in_sizes, int n_in,
                              void* d_out, int out_size) {
    const float* x      = (const float*)d_in[0];
    const float* ew     = (const float*)d_in[1];
    const float* gamma  = (const float*)d_in[2];
    const float* beta   = (const float*)d_in[3];
    const float* Wself  = (const float*)d_in[4];
    const float* Wneigh = (const float*)d_in[5];
    const float* bias   = (const float*)d_in[6];
    const float* lin_w  = (const float*)d_in[7];
    const float* lin_b  = (const float*)d_in[8];
    const int*   src    = (const int*)d_in[9];
    const int*   dst    = (const int*)d_in[10];
    float*       out    = (float*)d_out;

    (void)in_sizes; (void)n_in; (void)out_size;

    cudaFuncSetAttribute(k_gemm, cudaFuncAttributeMaxDynamicSharedMemorySize, GEMM_SMEM);

    float* hdev = nullptr;
    cudaGetSymbolAddress((void**)&hdev, g_h);

    k_prep0  <<<N_NODES / 256, 256>>>();
    k_count  <<<N_EDGES / 256, 256>>>(dst);
    k_scan   <<<1, 1024>>>();
    k_scatter<<<N_EDGES / 256, 256>>>(src, dst, ew);
    k_wprep  <<<(L * 2 * BPK_PER_CHUNK) / 256, 256>>>(Wself, Wneigh);
    k_stats  <<<256, 256>>>(x);

    // layer 0 (with 2 extra idempotent k_aggr launches for timing extraction)
    k_aggr<<<N_NODES * 32 / 256, 256>>>(x);
    k_aggr<<<N_NODES * 32 / 256, 256>>>(x);   // duplicate (measurement)
    k_aggr<<<N_NODES * 32 / 256, 256>>>(x);   // duplicate (measurement)
    k_gemm<<<N_NODES / 128, 256, GEMM_SMEM>>>(0, x, gamma, beta, bias,
                                              lin_w, lin_b, out, 0);
    // layer 1
    k_aggr<<<N_NODES * 32 / 256, 256>>>(hdev);
    k_gemm<<<N_NODES / 128, 256, GEMM_SMEM>>>(1, hdev, gamma, beta, bias + C,
                                              lin_w, lin_b, out, 0);
    // layer 2 (with 2 extra idempotent mode-1 k_gemm launches for timing extraction)
    k_aggr<<<N_NODES * 32 / 256, 256>>>(hdev);
    k_gemm<<<N_NODES / 128, 256, GEMM_SMEM>>>(2, hdev, gamma, beta, bias + 2 * C,
                                              lin_w, lin_b, out, 1);
    k_gemm<<<N_NODES / 128, 256, GEMM_SMEM>>>(2, hdev, gamma, beta, bias + 2 * C,
                                              lin_w, lin_b, out, 1);  // duplicate
    k_gemm<<<N_NODES / 128, 256, GEMM_SMEM>>>(2, hdev, gamma, beta, bias + 2 * C,
                                              lin_w, lin_b, out, 1);  // duplicate
}

// round 15
// speedup vs baseline: 2.0866x; 2.0866x over previous
#include <cuda_runtime.h>
#include <cuda_fp16.h>
#include <math.h>
#include <stdint.h>

#define N_NODES 65536
#define N_EDGES 524288
#define C 128
#define L 3
#define BN_EPS 1e-5f

// ---------------- scratch (device globals; no dynamic allocation) ----------------
__device__ float  g_h[N_NODES * C];       // layer output (input for next layer)
__device__ float  g_neigh[N_NODES * C];   // aggregated raw neighbor features (already /deg)
__device__ float  g_wbar[N_NODES];        // (sum of edge weights)/deg per node
__device__ float2 g_edge[N_EDGES];        // CSR-by-dst packed records: (src bits, log1p(w))
__device__ int    g_degcnt[N_NODES];
__device__ int    g_off[N_NODES + 1];
__device__ int    g_cursor[N_NODES];
__device__ float  g_deginv[N_NODES];
__device__ int    g_bsum[256];            // per-block count sums (scan phase 1)
__device__ int    g_boff[256];            // exclusive block offsets (scan phase 2)
__device__ float  g_stats[L * 2 * C];     // per-layer [sum(C) | sumsq(C)]
// pre-packed fp16 weight fragments in mma.sync per-lane order:
// [l][chunk][kstep(8)][nt16(16)][lane(32)] -> uint2 {b0, b1} (f16x2 each)
#define BPK_PER_CHUNK 4096
__device__ __align__(16) uint2 g_Bpk[L * 2 * BPK_PER_CHUNK];

// ---------------- helpers ----------------
__device__ __forceinline__ uint32_t pack_f16x2(float2 v) {
    __half2 h = __float22half2_rn(v);
    return *(uint32_t*)&h;
}
__device__ __forceinline__ void cvt_hilo_f16(float2 v, uint32_t& hi, uint32_t& lo) {
    __half2 h = __float22half2_rn(v);
    hi = *(uint32_t*)&h;
    float2 hf = __half22float2(h);
    __half2 l = __float22half2_rn(make_float2(v.x - hf.x, v.y - hf.y));
    lo = *(uint32_t*)&l;
}
__device__ __forceinline__ void mma_f16(float* d, const uint32_t* a, uint32_t b0, uint32_t b1) {
    asm volatile(
        "mma.sync.aligned.m16n8k16.row.col.f32.f16.f16.f32 "
        "{%0,%1,%2,%3}, {%4,%5,%6,%7}, {%8,%9}, {%0,%1,%2,%3};"
        : "+f"(d[0]), "+f"(d[1]), "+f"(d[2]), "+f"(d[3])
        : "r"(a[0]), "r"(a[1]), "r"(a[2]), "r"(a[3]), "r"(b0), "r"(b1));
}

// ---------------- prep ----------------
__global__ void k_prep0() {
    int i = blockIdx.x * blockDim.x + threadIdx.x;
    if (i < N_NODES) g_degcnt[i] = 0;
    if (i < L * 2 * C) g_stats[i] = 0.0f;
}
__global__ void k_count(const int* __restrict__ dst) {
    int e = blockIdx.x * blockDim.x + threadIdx.x;
    if (e < N_EDGES) atomicAdd(&g_degcnt[dst[e]], 1);
}

// scan phase 1: 256 blocks x 256 threads; block b sums counts [b*256, b*256+256)
__global__ void k_scan1() {
    __shared__ int red[256];
    int b = blockIdx.x, t = threadIdx.x;
    red[t] = g_degcnt[b * 256 + t];
    __syncthreads();
    #pragma unroll
    for (int o = 128; o > 0; o >>= 1) {
        if (t < o) red[t] += red[t + o];
        __syncthreads();
    }
    if (t == 0) g_bsum[b] = red[0];
}
// scan phase 2: 1 block x 256 threads; exclusive scan of 256 block sums
__global__ void k_scan2() {
    __shared__ int sp[256];
    int t = threadIdx.x;
    int v = g_bsum[t];
    sp[t] = v;
    __syncthreads();
    #pragma unroll
    for (int o = 1; o < 256; o <<= 1) {
        int u = (t >= o) ? sp[t - o] : 0;
        __syncthreads();
        sp[t] += u;
        __syncthreads();
    }
    g_boff[t] = sp[t] - v;                  // exclusive
    if (t == 0) g_off[N_NODES] = N_EDGES;
}
// scan phase 3: 256 blocks x 256 threads; in-block exclusive scan + finalize
__global__ void k_scan3() {
    __shared__ int sp[256];
    int b = blockIdx.x, t = threadIdx.x;
    int n = b * 256 + t;
    int cnt = g_degcnt[n];
    sp[t] = cnt;
    __syncthreads();
    #pragma unroll
    for (int o = 1; o < 256; o <<= 1) {
        int u = (t >= o) ? sp[t - o] : 0;
        __syncthreads();
        sp[t] += u;
        __syncthreads();
    }
    int off = g_boff[b] + sp[t] - cnt;      // global exclusive prefix
    g_off[n] = off;
    g_cursor[n] = off;
    g_deginv[n] = 1.0f / fmaxf((float)cnt, 1.0f);
}

__global__ void k_scatter(const int* __restrict__ src, const int* __restrict__ dst,
                          const float* __restrict__ ew) {
    int e = blockIdx.x * blockDim.x + threadIdx.x;
    if (e >= N_EDGES) return;
    int p = atomicAdd(&g_cursor[dst[e]], 1);
    g_edge[p] = make_float2(__int_as_float(src[e]), log1pf(ew[e]));
}

// ---------------- prep: weights -> pre-packed fp16 mma fragments ----------
__global__ void k_wprep(const float* __restrict__ Ws, const float* __restrict__ Wn) {
    int i = blockIdx.x * blockDim.x + threadIdx.x;   // 24576
    if (i >= L * 2 * BPK_PER_CHUNK) return;
    int lane  = i & 31;
    int nt    = (i >> 5) & 15;
    int kstep = (i >> 9) & 7;
    int chunk = (i >> 12) & 1;
    int l     = i >> 13;
    const float* W = (chunk ? Wn : Ws) + (size_t)l * 16384;
    int k0 = kstep * 16 + (lane & 3) * 2;
    int n  = nt * 8 + (lane >> 2);
    uint32_t b0 = pack_f16x2(make_float2(W[(k0 + 0) * 128 + n], W[(k0 + 1) * 128 + n]));
    uint32_t b1 = pack_f16x2(make_float2(W[(k0 + 8) * 128 + n], W[(k0 + 9) * 128 + n]));
    g_Bpk[i] = make_uint2(b0, b1);
}

// ---------------- one-time: BN column stats of x (layer 0) ----------------
__global__ void k_stats(const float* __restrict__ x) {
    int tid = threadIdx.x;
    int c = tid & (C - 1);
    int rr = tid >> 7;
    float s = 0.0f, s2 = 0.0f;
    for (int r = blockIdx.x * 2 + rr; r < N_NODES; r += gridDim.x * 2) {
        float v = x[(size_t)r * C + c];
        s += v; s2 += v * v;
    }
    atomicAdd(&g_stats[c], s);
    atomicAdd(&g_stats[C + c], s2);
}

// ---------------- per-layer: raw mean aggregation + wbar (R9 version) ----------
__global__ void k_aggr(const float* __restrict__ in) {
    int n = (blockIdx.x * blockDim.x + threadIdx.x) >> 5;
    int lane = threadIdx.x & 31;
    if (n >= N_NODES) return;
    int beg = g_off[n], end = g_off[n + 1];
    const float4* in4 = (const float4*)in;
    float4 a0 = make_float4(0.f, 0.f, 0.f, 0.f);
    float4 a1 = make_float4(0.f, 0.f, 0.f, 0.f);
    float ws = 0.f;
    int i = beg;
    for (; i + 4 <= end; i += 4) {
        float2 e0 = g_edge[i],     e1 = g_edge[i + 1];
        float2 e2 = g_edge[i + 2], e3 = g_edge[i + 3];
        float4 v0 = __ldg(&in4[(size_t)__float_as_int(e0.x) * 32 + lane]);
        float4 v1 = __ldg(&in4[(size_t)__float_as_int(e1.x) * 32 + lane]);
        float4 v2 = __ldg(&in4[(size_t)__float_as_int(e2.x) * 32 + lane]);
        float4 v3 = __ldg(&in4[(size_t)__float_as_int(e3.x) * 32 + lane]);
        a0.x += e0.y * v0.x; a0.y += e0.y * v0.y; a0.z += e0.y * v0.z; a0.w += e0.y * v0.w;
        a1.x += e1.y * v1.x; a1.y += e1.y * v1.y; a1.z += e1.y * v1.z; a1.w += e1.y * v1.w;
        a0.x += e2.y * v2.x; a0.y += e2.y * v2.y; a0.z += e2.y * v2.z; a0.w += e2.y * v2.w;
        a1.x += e3.y * v3.x; a1.y += e3.y * v3.y; a1.z += e3.y * v3.z; a1.w += e3.y * v3.w;
        ws += (e0.y + e1.y) + (e2.y + e3.y);
    }
    for (; i < end; i++) {
        float2 e = g_edge[i];
        float4 v = __ldg(&in4[(size_t)__float_as_int(e.x) * 32 + lane]);
        a0.x += e.y * v.x; a0.y += e.y * v.y; a0.z += e.y * v.z; a0.w += e.y * v.w;
        ws += e.y;
    }
    float di = g_deginv[n];
    float4 acc = make_float4((a0.x + a1.x) * di, (a0.y + a1.y) * di,
                             (a0.z + a1.z) * di, (a0.w + a1.w) * di);
    ((float4*)g_neigh)[(size_t)n * 32 + lane] = acc;
    if (lane == 0) g_wbar[n] = ws * di;
}

// ---------------- per-layer: 2-pass fp16 mma.sync dual GEMM, fused BN (R9) ----------
#define GEMM_SMEM (32768 + 2048)

__global__ __launch_bounds__(256, 2)
void k_gemm(int l, const float* __restrict__ Ain,
            const float* __restrict__ gamma, const float* __restrict__ beta,
            const float* __restrict__ bias,
            const float* __restrict__ lin_w, const float* __restrict__ lin_b,
            float* __restrict__ out, int mode) {
    extern __shared__ unsigned char dyn[];
    uint2* sB    = (uint2*)dyn;                 // 32KB: packed fp16 B fragments
    float* sSc   = (float*)(dyn + 32768);       // 128
    float* sSh   = sSc + 128;                   // 128
    float* sStat = sSh + 128;                   // 256

    int tid = threadIdx.x, wid = tid >> 5, lane = tid & 31;
    int row0 = blockIdx.x * 128;

    if (tid < 128) {
        float sum = g_stats[l * 2 * C + tid];
        float sq  = g_stats[l * 2 * C + C + tid];
        float mu  = sum * (1.0f / N_NODES);
        float var = sq * (1.0f / N_NODES) - mu * mu;
        float sc  = gamma[l * C + tid] * rsqrtf(var + BN_EPS);
        sSc[tid] = sc;
        sSh[tid] = beta[l * C + tid] - mu * sc;
    }
    if (tid < 256) sStat[tid] = 0.0f;

    float acc[16][4];
    #pragma unroll
    for (int nt = 0; nt < 16; nt++)
        #pragma unroll
        for (int q = 0; q < 4; q++) acc[nt][q] = 0.0f;

    int ar = row0 + wid * 16 + (lane >> 2);
    int ak = (lane & 3) * 2;
    float wb0 = g_wbar[ar], wb1 = g_wbar[ar + 8];

    #pragma unroll 1
    for (int chunk = 0; chunk < 2; chunk++) {
        if (chunk) __syncthreads();
        {
            const uint4* src = (const uint4*)(g_Bpk + (size_t)(l * 2 + chunk) * BPK_PER_CHUNK);
            uint4* dst = (uint4*)sB;
            #pragma unroll
            for (int it = 0; it < 8; it++) dst[it * 256 + tid] = src[it * 256 + tid];
        }
        __syncthreads();

        const float* Asrc = chunk ? g_neigh : Ain;
        float m0 = chunk ? wb0 : 1.0f;
        float m1 = chunk ? wb1 : 1.0f;

        #pragma unroll 2
        for (int ks = 0; ks < 8; ks++) {
            int kk = ks * 16 + ak;
            float2 scA = *(const float2*)&sSc[kk];
            float2 scB = *(const float2*)&sSc[kk + 8];
            float2 shA = *(const float2*)&sSh[kk];
            float2 shB = *(const float2*)&sSh[kk + 8];

            const float* p = Asrc + (size_t)ar * C + kk;
            float2 v0 = *(const float2*)(p);
            float2 v1 = *(const float2*)(p + 8 * C);
            float2 v2 = *(const float2*)(p + 8);
            float2 v3 = *(const float2*)(p + 8 * C + 8);
            v0.x = v0.x * scA.x + shA.x * m0; v0.y = v0.y * scA.y + shA.y * m0;
            v1.x = v1.x * scA.x + shA.x * m1; v1.y = v1.y * scA.y + shA.y * m1;
            v2.x = v2.x * scB.x + shB.x * m0; v2.y = v2.y * scB.y + shB.y * m0;
            v3.x = v3.x * scB.x + shB.x * m1; v3.y = v3.y * scB.y + shB.y * m1;

            uint32_t ahi[4], alo[4];
            cvt_hilo_f16(v0, ahi[0], alo[0]);
            cvt_hilo_f16(v1, ahi[1], alo[1]);
            cvt_hilo_f16(v2, ahi[2], alo[2]);
            cvt_hilo_f16(v3, ahi[3], alo[3]);

            #pragma unroll
            for (int nt = 0; nt < 16; nt++) {
                uint2 b = sB[(ks * 16 + nt) * 32 + lane];
                mma_f16(acc[nt], ahi, b.x, b.y);
                mma_f16(acc[nt], alo, b.x, b.y);
            }
        }
    }

    if (mode == 0) {
        #pragma unroll
        for (int nt = 0; nt < 16; nt++) {
            int col = nt * 8 + (lane & 3) * 2;
            float b0 = bias[col], b1 = bias[col + 1];
            float o00 = fmaxf(acc[nt][0] + b0, 0.f);
            float o01 = fmaxf(acc[nt][1] + b1, 0.f);
            float o10 = fmaxf(acc[nt][2] + b0, 0.f);
            float o11 = fmaxf(acc[nt][3] + b1, 0.f);
            *(float2*)(g_h + (size_t)ar * C + col)       = make_float2(o00, o01);
            *(float2*)(g_h + (size_t)(ar + 8) * C + col) = make_float2(o10, o11);
            float s0 = o00 + o10, s1 = o01 + o11;
            float q0 = o00 * o00 + o10 * o10, q1 = o01 * o01 + o11 * o11;
            #pragma unroll
            for (int off = 16; off >= 4; off >>= 1) {
                s0 += __shfl_down_sync(0xffffffffu, s0, off);
                s1 += __shfl_down_sync(0xffffffffu, s1, off);
                q0 += __shfl_down_sync(0xffffffffu, q0, off);
                q1 += __shfl_down_sync(0xffffffffu, q1, off);
            }
            if (lane < 4) {
                atomicAdd(&sStat[col],           s0);
                atomicAdd(&sStat[col + 1],       s1);
                atomicAdd(&sStat[128 + col],     q0);
                atomicAdd(&sStat[128 + col + 1], q1);
            }
        }
        __syncthreads();
        if (tid < 128) {
            atomicAdd(&g_stats[(l + 1) * 2 * C + tid],     sStat[tid]);
            atomicAdd(&g_stats[(l + 1) * 2 * C + C + tid], sStat[128 + tid]);
        }
    } else {
        float p0 = 0.f, p1 = 0.f;
        #pragma unroll
        for (int nt = 0; nt < 16; nt++) {
            int col = nt * 8 + (lane & 3) * 2;
            float b0 = bias[col], b1 = bias[col + 1];
            float lw0 = lin_w[col], lw1 = lin_w[col + 1];
            float o00 = fmaxf(acc[nt][0] + b0, 0.f);
            float o01 = fmaxf(acc[nt][1] + b1, 0.f);
            float o10 = fmaxf(acc[nt][2] + b0, 0.f);
            float o11 = fmaxf(acc[nt][3] + b1, 0.f);
            p0 += o00 * lw0 + o01 * lw1;
            p1 += o10 * lw0 + o11 * lw1;
        }
        p0 += __shfl_xor_sync(0xffffffffu, p0, 1);
        p0 += __shfl_xor_sync(0xffffffffu, p0, 2);
        p1 += __shfl_xor_sync(0xffffffffu, p1, 1);
        p1 += __shfl_xor_sync(0xffffffffu, p1, 2);
        if ((lane & 3) == 0) {
            float lb = lin_b[0];
            out[ar] = p0 + lb;
            out[ar + 8] = p1 + lb;
        }
    }
}

// ---------------- launch ----------------
extern "C" void kernel_launch(void* const* d_in, const int* in_sizes, int n_in,
                              void* d_out, int out_size) {
    const float* x      = (const float*)d_in[0];
    const float* ew     = (const float*)d_in[1];
    const float* gamma  = (const float*)d_in[2];
    const float* beta   = (const float*)d_in[3];
    const float* Wself  = (const float*)d_in[4];
    const float* Wneigh = (const float*)d_in[5];
    const float* bias   = (const float*)d_in[6];
    const float* lin_w  = (const float*)d_in[7];
    const float* lin_b  = (const float*)d_in[8];
    const int*   src    = (const int*)d_in[9];
    const int*   dst    = (const int*)d_in[10];
    float*       out    = (float*)d_out;

    (void)in_sizes; (void)n_in; (void)out_size;

    cudaFuncSetAttribute(k_gemm, cudaFuncAttributeMaxDynamicSharedMemorySize, GEMM_SMEM);

    float* hdev = nullptr;
    cudaGetSymbolAddress((void**)&hdev, g_h);

    k_prep0  <<<N_NODES / 256, 256>>>();
    k_count  <<<N_EDGES / 256, 256>>>(dst);
    k_scan1  <<<256, 256>>>();
    k_scan2  <<<1, 256>>>();
    k_scan3  <<<256, 256>>>();
    k_scatter<<<N_EDGES / 256, 256>>>(src, dst, ew);
    k_wprep  <<<(L * 2 * BPK_PER_CHUNK) / 256, 256>>>(Wself, Wneigh);
    k_stats  <<<256, 256>>>(x);

    for (int l = 0; l < L; l++) {
        const float* in = (l == 0) ? x : hdev;
        k_aggr<<<N_NODES * 32 / 256, 256>>>(in);
        k_gemm<<<N_NODES / 128, 256, GEMM_SMEM>>>(l, in, gamma, beta,
                                                  bias + (size_t)l * C,
                                                  lin_w, lin_b, out,
                                                  (l == L - 1) ? 1 : 0);
    }
}